// round 12
// baseline (speedup 1.0000x reference)
#include <cuda_runtime.h>
#include <cuda_bf16.h>
#include <cstdint>

// BiLinearInterpolation (spatial transformer sampler)
// X:     [B=16, H=512, W=512, C=16] float32  (channels-last)
// theta: [B=16, 6]                  float32
// out:   [B=16, 256, 256, 16]       float32
//
// Numerics (FROZEN — verified rel_err 2.777e-5):
//  - linspace: g = rn(-1 + rn(i * rn(2/255)))
//  - einsum:   sg = rn(fma(t1,gy, rn(t0*gx)) + t2)   (cublas ascending-K)
//  - scale:    x  = rn(rn(sg+1) * 256)
//  - trunc-to-int, clamp, weights = rn(rn(sub)*rn(sub))  (no fma)
//  - blend:    ((rn(wa*pa)+rn(wb*pb))+rn(wc*pc))+rn(wd*pd)  (no fma)
//    Split across lanes: lo computes t=rn(ma+mb); shfl; hi computes
//    rn(rn(t+mc)+md) — same association, bit-identical.
//
// Octet layout: 8 lanes per pixel. c4 = lane&3 selects the 16B channel
// chunk; hi = lane bit2 selects x0 (corners a,b) vs x1 (corners c,d).
// One LDG per input row-pair covers 128B contiguous per octet (a+c fused,
// b+d fused) -> fewer L1 wavefronts than 4 separate 64B corner loads.
// Each thread handles 2 pixels (rows r, r+128); 4 LDG front-batched.

static constexpr int B     = 16;
static constexpr int H     = 512;
static constexpr int W     = 512;
static constexpr int OUT_H = 256;
static constexpr int OUT_W = 256;
static constexpr int NPIX  = OUT_H * OUT_W;            // 65536
static constexpr int C4    = 4;                        // float4 quarters

struct OctInfo {
    unsigned i1, i2;           // float4 indices: row y0 and row y1, at x0 or x1
    float wa, wb, wc, wd;
};

__device__ __forceinline__ OctInfo oct_info(float x, float y, unsigned baseb,
                                            unsigned c4, unsigned hi)
{
    int x0 = (int)x;           // cvt.rzi — trunc toward zero
    int y0 = (int)y;
    int x1 = x0 + 1;
    int y1 = y0 + 1;
    x0 = min(max(x0, 0), W - 1);
    x1 = min(max(x1, 0), W - 1);
    y0 = min(max(y0, 0), H - 1);
    y1 = min(max(y1, 0), H - 1);

    const float x0f = (float)x0, x1f = (float)x1;
    const float y0f = (float)y0, y1f = (float)y1;

    const float dxa = __fsub_rn(x1f, x);
    const float dxb = __fsub_rn(x, x0f);
    const float dya = __fsub_rn(y1f, y);
    const float dyb = __fsub_rn(y, y0f);

    OctInfo p;
    p.wa = __fmul_rn(dxa, dya);
    p.wb = __fmul_rn(dxa, dyb);
    p.wc = __fmul_rn(dxb, dya);
    p.wd = __fmul_rn(dxb, dyb);

    const unsigned xs = hi ? (unsigned)x1 : (unsigned)x0;
    p.i1 = (baseb + (unsigned)y0 * W + xs) * C4 + c4;   // a (lo) / c (hi)
    p.i2 = (baseb + (unsigned)y1 * W + xs) * C4 + c4;   // b (lo) / d (hi)
    return p;
}

// lo lanes: t = rn(rn(wa*p1) + rn(wb*p2))  (p1=a, p2=b)
__device__ __forceinline__ float4 partial_ab(float wa, float wb, float4 p1, float4 p2)
{
    float4 t;
    t.x = __fadd_rn(__fmul_rn(wa, p1.x), __fmul_rn(wb, p2.x));
    t.y = __fadd_rn(__fmul_rn(wa, p1.y), __fmul_rn(wb, p2.y));
    t.z = __fadd_rn(__fmul_rn(wa, p1.z), __fmul_rn(wb, p2.z));
    t.w = __fadd_rn(__fmul_rn(wa, p1.w), __fmul_rn(wb, p2.w));
    return t;
}

__device__ __forceinline__ float4 shfl4_xor4(float4 v)
{
    float4 r;
    r.x = __shfl_xor_sync(0xFFFFFFFFu, v.x, 4);
    r.y = __shfl_xor_sync(0xFFFFFFFFu, v.y, 4);
    r.z = __shfl_xor_sync(0xFFFFFFFFu, v.z, 4);
    r.w = __shfl_xor_sync(0xFFFFFFFFu, v.w, 4);
    return r;
}

// hi lanes: rn(rn(t + rn(wc*p1)) + rn(wd*p2))  (p1=c, p2=d)
__device__ __forceinline__ float4 finish_cd(float4 t, float wc, float wd,
                                            float4 p1, float4 p2)
{
    float4 o;
    o.x = __fadd_rn(__fadd_rn(t.x, __fmul_rn(wc, p1.x)), __fmul_rn(wd, p2.x));
    o.y = __fadd_rn(__fadd_rn(t.y, __fmul_rn(wc, p1.y)), __fmul_rn(wd, p2.y));
    o.z = __fadd_rn(__fadd_rn(t.z, __fmul_rn(wc, p1.z)), __fmul_rn(wd, p2.z));
    o.w = __fadd_rn(__fadd_rn(t.w, __fmul_rn(wc, p1.w)), __fmul_rn(wd, p2.w));
    return o;
}

__global__ __launch_bounds__(256)
void bilinear_sampler_kernel(const float* __restrict__ X,
                             const float* __restrict__ theta,
                             float* __restrict__ out)
{
    const unsigned tid = blockIdx.x * blockDim.x + threadIdx.x;
    // 4,194,304 threads; octet (8 lanes) per pixel-slot; each slot covers
    // pixels (b, row, col) and (b, row+128, col).

    const unsigned c4  = tid & 3u;
    const unsigned hi  = (tid >> 2) & 1u;      // 0: a/b side (x0), 1: c/d side (x1)
    const unsigned oct = tid >> 3;             // [0, 524288)
    const unsigned b   = oct >> 15;            // / 32768
    const unsigned rem = oct & 32767u;
    const unsigned row = rem >> 8;             // [0, 128)
    const unsigned col = rem & 255u;
    const unsigned row2 = row + 128u;

    const float DELTA = 2.0f / 255.0f;
    const float gx  = __fadd_rn(-1.0f, __fmul_rn((float)col,  DELTA));
    const float gy0 = __fadd_rn(-1.0f, __fmul_rn((float)row,  DELTA));
    const float gy1 = __fadd_rn(-1.0f, __fmul_rn((float)row2, DELTA));

    const float* th = theta + b * 6;
    const float t0 = __ldg(th + 0), t1 = __ldg(th + 1), t2 = __ldg(th + 2);
    const float t3 = __ldg(th + 3), t4 = __ldg(th + 4), t5 = __ldg(th + 5);

    const float m0x = __fmul_rn(t0, gx);
    const float m1x = __fmul_rn(t3, gx);

    const float sg0a = __fadd_rn(__fmaf_rn(t1, gy0, m0x), t2);
    const float sg1a = __fadd_rn(__fmaf_rn(t4, gy0, m1x), t5);
    const float sg0b = __fadd_rn(__fmaf_rn(t1, gy1, m0x), t2);
    const float sg1b = __fadd_rn(__fmaf_rn(t4, gy1, m1x), t5);

    const float xA = __fmul_rn(__fadd_rn(sg0a, 1.0f), 256.0f);
    const float yA = __fmul_rn(__fadd_rn(sg1a, 1.0f), 256.0f);
    const float xB = __fmul_rn(__fadd_rn(sg0b, 1.0f), 256.0f);
    const float yB = __fmul_rn(__fadd_rn(sg1b, 1.0f), 256.0f);

    const unsigned baseb = b * (unsigned)(H * W);
    const OctInfo A  = oct_info(xA, yA, baseb, c4, hi);
    const OctInfo Bo = oct_info(xB, yB, baseb, c4, hi);

    const float4* Xf4 = (const float4*)X;

    // 4 independent loads front-batched; each warp LDG covers 128B-contiguous
    // octet spans (a+c fused / b+d fused).
    const float4 p1A = __ldg(Xf4 + A.i1);
    const float4 p2A = __ldg(Xf4 + A.i2);
    const float4 p1B = __ldg(Xf4 + Bo.i1);
    const float4 p2B = __ldg(Xf4 + Bo.i2);

    // lo-lane partial (garbage on hi lanes, ignored there)
    const float4 tA = partial_ab(A.wa, A.wb, p1A, p2A);
    const float4 tB = partial_ab(Bo.wa, Bo.wb, p1B, p2B);

    const float4 trA = shfl4_xor4(tA);   // hi lanes receive lo partial
    const float4 trB = shfl4_xor4(tB);

    const float4 oA = finish_cd(trA, A.wc, A.wd, p1A, p2A);
    const float4 oB = finish_cd(trB, Bo.wc, Bo.wd, p1B, p2B);

    if (hi) {
        const unsigned o0 = (b * (unsigned)NPIX + row * 256u + col) * 4u + c4;
        __stcs(((float4*)out) + o0,           oA);
        __stcs(((float4*)out) + o0 + 131072u, oB);
    }
}

extern "C" void kernel_launch(void* const* d_in, const int* in_sizes, int n_in,
                              void* d_out, int out_size)
{
    const float* X     = (const float*)d_in[0];
    const float* theta = (const float*)d_in[1];
    float* out         = (float*)d_out;

    const int total = 4194304;             // B * NPIX/2 slots * 8 lanes
    const int tpb = 256;
    bilinear_sampler_kernel<<<total / tpb, tpb>>>(X, theta, out);
}

// round 13
// speedup vs baseline: 1.1404x; 1.1404x over previous
#include <cuda_runtime.h>
#include <cuda_bf16.h>
#include <cstdint>

// BiLinearInterpolation (spatial transformer sampler)
// X:     [B=16, H=512, W=512, C=16] float32  (channels-last)
// theta: [B=16, 6]                  float32
// out:   [B=16, 256, 256, 16]       float32
//
// Numerics (FROZEN — verified rel_err 2.777e-5):
//  - linspace: g = rn(-1 + rn(i * rn(2/255)))
//  - einsum:   sg = rn(fma(t1,gy, rn(t0*gx)) + t2)   (cublas ascending-K)
//  - scale:    x  = rn(rn(sg+1) * 256)
//  - trunc-to-int, clamp, weights = rn(rn(sub)*rn(sub))  (no fma)
//  - blend:    ((rn(wa*pa)+rn(wb*pb))+rn(wc*pc))+rn(wd*pd)  (no fma)
//
// Perf layout (round-10 winner, confirmed near wavefront/latency floor):
// lanes 4k..4k+3 share a pixel; 2 pixels per thread (rows r, r+128) with
// 8 corner loads front-batched (MLP=8); 32-bit addressing; __stcs stores;
// regs<=32 keeps full 64-warp residency.
// Round-12 trims: A-loads issued before B's coordinate math; output index
// simplified to tid + (b<<17).

static constexpr int B     = 16;
static constexpr int H     = 512;
static constexpr int W     = 512;

__device__ __forceinline__ float4 blend_exact(float wa, float wb, float wc, float wd,
                                              float4 pa, float4 pb, float4 pc, float4 pd)
{
    float4 o;
    o.x = __fadd_rn(__fadd_rn(__fadd_rn(__fmul_rn(wa, pa.x), __fmul_rn(wb, pb.x)),
                              __fmul_rn(wc, pc.x)), __fmul_rn(wd, pd.x));
    o.y = __fadd_rn(__fadd_rn(__fadd_rn(__fmul_rn(wa, pa.y), __fmul_rn(wb, pb.y)),
                              __fmul_rn(wc, pc.y)), __fmul_rn(wd, pd.y));
    o.z = __fadd_rn(__fadd_rn(__fadd_rn(__fmul_rn(wa, pa.z), __fmul_rn(wb, pb.z)),
                              __fmul_rn(wc, pc.z)), __fmul_rn(wd, pd.z));
    o.w = __fadd_rn(__fadd_rn(__fadd_rn(__fmul_rn(wa, pa.w), __fmul_rn(wb, pb.w)),
                              __fmul_rn(wc, pc.w)), __fmul_rn(wd, pd.w));
    return o;
}

struct PixInfo {
    unsigned ia, ib, ic, id;   // float4 indices
    float wa, wb, wc, wd;
};

__device__ __forceinline__ PixInfo pixel_info(float x, float y, unsigned baseb, unsigned c4)
{
    int x0 = (int)x;           // cvt.rzi — trunc toward zero
    int y0 = (int)y;
    int x1 = x0 + 1;
    int y1 = y0 + 1;
    x0 = min(max(x0, 0), W - 1);
    x1 = min(max(x1, 0), W - 1);
    y0 = min(max(y0, 0), H - 1);
    y1 = min(max(y1, 0), H - 1);

    const float x0f = (float)x0, x1f = (float)x1;
    const float y0f = (float)y0, y1f = (float)y1;

    const float dxa = __fsub_rn(x1f, x);
    const float dxb = __fsub_rn(x, x0f);
    const float dya = __fsub_rn(y1f, y);
    const float dyb = __fsub_rn(y, y0f);

    PixInfo p;
    p.wa = __fmul_rn(dxa, dya);
    p.wb = __fmul_rn(dxa, dyb);
    p.wc = __fmul_rn(dxb, dya);
    p.wd = __fmul_rn(dxb, dyb);

    const unsigned r0 = baseb + (unsigned)y0 * W;
    const unsigned r1 = baseb + (unsigned)y1 * W;
    p.ia = (r0 + (unsigned)x0) * 4u + c4;
    p.ib = (r1 + (unsigned)x0) * 4u + c4;
    p.ic = (r0 + (unsigned)x1) * 4u + c4;
    p.id = (r1 + (unsigned)x1) * 4u + c4;
    return p;
}

__global__ __launch_bounds__(256)
void bilinear_sampler_kernel(const float* __restrict__ X,
                             const float* __restrict__ theta,
                             float* __restrict__ out)
{
    const unsigned tid = blockIdx.x * blockDim.x + threadIdx.x;
    // 2,097,152 threads; each does pixels (b, row, col) and (b, row+128, col)

    const unsigned c4  = tid & 3u;
    const unsigned idx = tid >> 2;             // [0, 524288)
    const unsigned b   = idx >> 15;            // / 32768
    const unsigned rem = idx & 32767u;
    const unsigned row = rem >> 8;             // [0, 128)
    const unsigned col = rem & 255u;

    const float DELTA = 2.0f / 255.0f;
    const float gx  = __fadd_rn(-1.0f, __fmul_rn((float)col, DELTA));
    const float gy0 = __fadd_rn(-1.0f, __fmul_rn((float)row, DELTA));

    const float* th = theta + b * 6;
    const float t0 = __ldg(th + 0), t1 = __ldg(th + 1), t2 = __ldg(th + 2);
    const float t3 = __ldg(th + 3), t4 = __ldg(th + 4), t5 = __ldg(th + 5);

    const float m0x = __fmul_rn(t0, gx);       // shared across both pixels
    const float m1x = __fmul_rn(t3, gx);

    const unsigned baseb = b * (unsigned)(H * W);
    const float4* Xf4 = (const float4*)X;

    // ---- pixel A: compute info and issue its 4 loads ASAP ----
    const float sg0a = __fadd_rn(__fmaf_rn(t1, gy0, m0x), t2);
    const float sg1a = __fadd_rn(__fmaf_rn(t4, gy0, m1x), t5);
    const float xA = __fmul_rn(__fadd_rn(sg0a, 1.0f), 256.0f);
    const float yA = __fmul_rn(__fadd_rn(sg1a, 1.0f), 256.0f);
    const PixInfo A = pixel_info(xA, yA, baseb, c4);

    const float4 paA = __ldg(Xf4 + A.ia);
    const float4 pbA = __ldg(Xf4 + A.ib);
    const float4 pcA = __ldg(Xf4 + A.ic);
    const float4 pdA = __ldg(Xf4 + A.id);

    // ---- pixel B: math runs under A's load shadow ----
    const float gy1 = __fadd_rn(-1.0f, __fmul_rn((float)(row + 128u), DELTA));
    const float sg0b = __fadd_rn(__fmaf_rn(t1, gy1, m0x), t2);
    const float sg1b = __fadd_rn(__fmaf_rn(t4, gy1, m1x), t5);
    const float xB = __fmul_rn(__fadd_rn(sg0b, 1.0f), 256.0f);
    const float yB = __fmul_rn(__fadd_rn(sg1b, 1.0f), 256.0f);
    const PixInfo Bi = pixel_info(xB, yB, baseb, c4);

    const float4 paB = __ldg(Xf4 + Bi.ia);
    const float4 pbB = __ldg(Xf4 + Bi.ib);
    const float4 pcB = __ldg(Xf4 + Bi.ic);
    const float4 pdB = __ldg(Xf4 + Bi.id);

    const float4 oA = blend_exact(A.wa, A.wb, A.wc, A.wd, paA, pbA, pcA, pdA);
    const float4 oB = blend_exact(Bi.wa, Bi.wb, Bi.wc, Bi.wd, paB, pbB, pcB, pdB);

    // output float4 index: (b*65536 + row*256 + col)*4 + c4 == tid + b*131072
    const unsigned o0 = tid + (b << 17);
    __stcs(((float4*)out) + o0,           oA);   // row     (+0)
    __stcs(((float4*)out) + o0 + 131072u, oB);   // row+128 (+128*256*4)
}

extern "C" void kernel_launch(void* const* d_in, const int* in_sizes, int n_in,
                              void* d_out, int out_size)
{
    const float* X     = (const float*)d_in[0];
    const float* theta = (const float*)d_in[1];
    float* out         = (float*)d_out;

    const int total = 2097152;             // B*NPIX*C4 / 2
    const int tpb = 256;
    bilinear_sampler_kernel<<<total / tpb, tpb>>>(X, theta, out);
}

// round 14
// speedup vs baseline: 1.1696x; 1.0257x over previous
#include <cuda_runtime.h>
#include <cuda_bf16.h>
#include <cstdint>

// BiLinearInterpolation (spatial transformer sampler)
// X:     [B=16, H=512, W=512, C=16] float32  (channels-last)
// theta: [B=16, 6]                  float32
// out:   [B=16, 256, 256, 16]       float32
//
// Numerics (FROZEN — verified rel_err 2.777e-5):
//  - linspace: g = rn(-1 + rn(i * rn(2/255)))
//  - einsum:   sg = rn(fma(t1,gy, rn(t0*gx)) + t2)   (cublas ascending-K)
//  - scale:    x  = rn(rn(sg+1) * 256)
//  - trunc-to-int, clamp, weights = rn(rn(sub)*rn(sub))  (no fma)
//  - blend:    ((rn(wa*pa)+rn(wb*pb))+rn(wc*pc))+rn(wd*pd)  (no fma)
//
// Perf layout (round-10 winner): lanes 4k..4k+3 share a pixel; 2 pixels per
// thread (rows r, r+128); both PixInfos computed BEFORE the 8 front-batched
// corner loads (this ordering compiles to 32 regs); __stcs streaming stores.
// __launch_bounds__(256, 8) pins regs<=32 => full 64-warp residency.

static constexpr int B     = 16;
static constexpr int H     = 512;
static constexpr int W     = 512;
static constexpr int OUT_H = 256;
static constexpr int OUT_W = 256;
static constexpr int NPIX  = OUT_H * OUT_W;            // 65536
static constexpr int C4    = 4;                        // float4 quarters

__device__ __forceinline__ float4 blend_exact(float wa, float wb, float wc, float wd,
                                              float4 pa, float4 pb, float4 pc, float4 pd)
{
    float4 o;
    o.x = __fadd_rn(__fadd_rn(__fadd_rn(__fmul_rn(wa, pa.x), __fmul_rn(wb, pb.x)),
                              __fmul_rn(wc, pc.x)), __fmul_rn(wd, pd.x));
    o.y = __fadd_rn(__fadd_rn(__fadd_rn(__fmul_rn(wa, pa.y), __fmul_rn(wb, pb.y)),
                              __fmul_rn(wc, pc.y)), __fmul_rn(wd, pd.y));
    o.z = __fadd_rn(__fadd_rn(__fadd_rn(__fmul_rn(wa, pa.z), __fmul_rn(wb, pb.z)),
                              __fmul_rn(wc, pc.z)), __fmul_rn(wd, pd.z));
    o.w = __fadd_rn(__fadd_rn(__fadd_rn(__fmul_rn(wa, pa.w), __fmul_rn(wb, pb.w)),
                              __fmul_rn(wc, pc.w)), __fmul_rn(wd, pd.w));
    return o;
}

struct PixInfo {
    unsigned ia, ib, ic, id;   // float4 indices
    float wa, wb, wc, wd;
};

__device__ __forceinline__ PixInfo pixel_info(float x, float y, unsigned baseb, unsigned c4)
{
    int x0 = (int)x;           // cvt.rzi — trunc toward zero
    int y0 = (int)y;
    int x1 = x0 + 1;
    int y1 = y0 + 1;
    x0 = min(max(x0, 0), W - 1);
    x1 = min(max(x1, 0), W - 1);
    y0 = min(max(y0, 0), H - 1);
    y1 = min(max(y1, 0), H - 1);

    const float x0f = (float)x0, x1f = (float)x1;
    const float y0f = (float)y0, y1f = (float)y1;

    const float dxa = __fsub_rn(x1f, x);
    const float dxb = __fsub_rn(x, x0f);
    const float dya = __fsub_rn(y1f, y);
    const float dyb = __fsub_rn(y, y0f);

    PixInfo p;
    p.wa = __fmul_rn(dxa, dya);
    p.wb = __fmul_rn(dxa, dyb);
    p.wc = __fmul_rn(dxb, dya);
    p.wd = __fmul_rn(dxb, dyb);

    const unsigned r0 = baseb + (unsigned)y0 * W;
    const unsigned r1 = baseb + (unsigned)y1 * W;
    p.ia = (r0 + (unsigned)x0) * C4 + c4;
    p.ib = (r1 + (unsigned)x0) * C4 + c4;
    p.ic = (r0 + (unsigned)x1) * C4 + c4;
    p.id = (r1 + (unsigned)x1) * C4 + c4;
    return p;
}

__global__ __launch_bounds__(256, 8)
void bilinear_sampler_kernel(const float* __restrict__ X,
                             const float* __restrict__ theta,
                             float* __restrict__ out)
{
    const unsigned tid = blockIdx.x * blockDim.x + threadIdx.x;
    // 2,097,152 threads; each does pixels (b, row, col) and (b, row+128, col)

    const unsigned c4  = tid & 3u;
    const unsigned idx = tid >> 2;             // [0, 524288)
    const unsigned b   = idx >> 15;            // / 32768
    const unsigned rem = idx & 32767u;
    const unsigned row = rem >> 8;             // [0, 128)
    const unsigned col = rem & 255u;
    const unsigned row2 = row + 128u;

    const float DELTA = 2.0f / 255.0f;
    const float gx  = __fadd_rn(-1.0f, __fmul_rn((float)col,  DELTA));
    const float gy0 = __fadd_rn(-1.0f, __fmul_rn((float)row,  DELTA));
    const float gy1 = __fadd_rn(-1.0f, __fmul_rn((float)row2, DELTA));

    const float* th = theta + b * 6;
    const float t0 = __ldg(th + 0), t1 = __ldg(th + 1), t2 = __ldg(th + 2);
    const float t3 = __ldg(th + 3), t4 = __ldg(th + 4), t5 = __ldg(th + 5);

    const float m0x = __fmul_rn(t0, gx);       // shared across both pixels
    const float m1x = __fmul_rn(t3, gx);

    const float sg0a = __fadd_rn(__fmaf_rn(t1, gy0, m0x), t2);
    const float sg1a = __fadd_rn(__fmaf_rn(t4, gy0, m1x), t5);
    const float sg0b = __fadd_rn(__fmaf_rn(t1, gy1, m0x), t2);
    const float sg1b = __fadd_rn(__fmaf_rn(t4, gy1, m1x), t5);

    const float xA = __fmul_rn(__fadd_rn(sg0a, 1.0f), 256.0f);
    const float yA = __fmul_rn(__fadd_rn(sg1a, 1.0f), 256.0f);
    const float xB = __fmul_rn(__fadd_rn(sg0b, 1.0f), 256.0f);
    const float yB = __fmul_rn(__fadd_rn(sg1b, 1.0f), 256.0f);

    const unsigned baseb = b * (unsigned)(H * W);
    const PixInfo A = pixel_info(xA, yA, baseb, c4);
    const PixInfo Bx = pixel_info(xB, yB, baseb, c4);

    const float4* Xf4 = (const float4*)X;

    // 8 independent loads up front (MLP=8)
    const float4 paA = __ldg(Xf4 + A.ia);
    const float4 pbA = __ldg(Xf4 + A.ib);
    const float4 pcA = __ldg(Xf4 + A.ic);
    const float4 pdA = __ldg(Xf4 + A.id);
    const float4 paB = __ldg(Xf4 + Bx.ia);
    const float4 pbB = __ldg(Xf4 + Bx.ib);
    const float4 pcB = __ldg(Xf4 + Bx.ic);
    const float4 pdB = __ldg(Xf4 + Bx.id);

    const float4 oA = blend_exact(A.wa, A.wb, A.wc, A.wd, paA, pbA, pcA, pdA);
    const float4 oB = blend_exact(Bx.wa, Bx.wb, Bx.wc, Bx.wd, paB, pbB, pcB, pdB);

    // output float4 index: (b*65536 + row*256 + col)*4 + c4 == tid + b*131072
    const unsigned o0 = tid + (b << 17);
    __stcs(((float4*)out) + o0,           oA);   // row
    __stcs(((float4*)out) + o0 + 131072u, oB);   // row+128
}

extern "C" void kernel_launch(void* const* d_in, const int* in_sizes, int n_in,
                              void* d_out, int out_size)
{
    const float* X     = (const float*)d_in[0];
    const float* theta = (const float*)d_in[1];
    float* out         = (float*)d_out;

    const int total = 2097152;             // B*NPIX*C4 / 2
    const int tpb = 256;
    bilinear_sampler_kernel<<<total / tpb, tpb>>>(X, theta, out);
}